// round 10
// baseline (speedup 1.0000x reference)
#include <cuda_runtime.h>

// Problem constants (fixed instance: B=32, T=512, C=6625, L=32)
#define BB 32
#define TT 512
#define TH 304       // meet point: fwd (double-step) 304 t, bwd (single) 208 t
#define CC 6625
#define LL 32
#define SS 65        // 2L+1 extended states
#define NSC 33       // stored emission rows per batch: 32 labels + blank
#define BLANK_ID 6624
#define LOG2E 1.4426950408889634f
#define LN2d  0.6931471805599453
#define CSHIFT 10.0f     // constant log2 boost per emission
#define RN_TARGET 45     // renorm target exponent (cadence 16 t)

// Static device scratch (no runtime allocation). [b][s][t] layout, s-major.
__device__ __align__(128) float g_emit[(size_t)BB * NSC * TT];
__device__ float g_partial[BB];
__device__ int   g_cnt[BB];      // per-batch gather-completion counters (zero-init)
__device__ int   g_done = 0;     // batch-mean completion counter

__device__ __forceinline__ float ex2f_(float x) {
    float y; asm("ex2.approx.ftz.f32 %0, %1;" : "=f"(y) : "f"(x)); return y;
}
__device__ __forceinline__ float lg2f_(float x) {
    float y; asm("lg2.approx.ftz.f32 %0, %1;" : "=f"(y) : "f"(x)); return y;
}
__device__ __forceinline__ float4 ldcg4_(const float* p) {
    return __ldcg((const float4*)p);
}
// Plain L2-only scalar load (no .nc read-only path, no policy) — the
// differential under test: does this fill 32B sectors instead of 128B lines?
__device__ __forceinline__ float ldcg_(const float* p) {
    float r;
    asm volatile("ld.global.cg.f32 %0, [%1];" : "=f"(r) : "l"(p));
    return r;
}

// --- forward DOUBLE step (r5-validated composition; lm via shuffle) --------
#define FDS(el0, el1, eb0, eb1) do {                                \
    float pO_ = __shfl_up_sync(0xffffffffu, aO, 1);                 \
    float pE_ = __shfl_up_sync(0xffffffffu, aE, 1);                 \
    float qO_ = __shfl_up_sync(0xffffffffu, aO, 2);                 \
    float lm_ = __shfl_up_sync(0xffffffffu, (el0), 1);              \
    float s0_ = aO + aE;                                            \
    float x0_ = aX + aO;                                            \
    float u_  = fmaf(pO_, zb, aE);                                  \
    float v_  = fmaf(pO_, za, s0_);                                 \
    float w_  = fmaf(qO_, pza, pO_ + pE_);                          \
    float ub_ = u_ * (eb0), vl_ = v_ * (el0), x1_ = x0_ * (eb0);    \
    aE = fmaf(w_, lm_ * zb, ub_) * (eb1);                           \
    aO = fmaf(w_, lm_ * za, ub_ + vl_) * (el1);                     \
    aX = fmaf(v_, (el0), x1_) * (eb1);                              \
} while (0)

#define FDSP(el0, el1, eb0, eb1, tcur) do {                         \
    float pO_ = __shfl_up_sync(0xffffffffu, aO, 1);                 \
    float pE_ = __shfl_up_sync(0xffffffffu, aE, 1);                 \
    float qO_ = __shfl_up_sync(0xffffffffu, aO, 2);                 \
    float lm_ = __shfl_up_sync(0xffffffffu, (el0), 1);              \
    float s0_ = aO + aE;                                            \
    float x0_ = aX + aO;                                            \
    float u_  = fmaf(pO_, zb, aE);                                  \
    float v_  = fmaf(pO_, za, s0_);                                 \
    float w_  = fmaf(qO_, pza, pO_ + pE_);                          \
    float ub_ = u_ * (eb0), vl_ = v_ * (el0), x1_ = x0_ * (eb0);    \
    float e2_ = fmaf(w_, lm_ * zb, ub_) * (eb1);                    \
    float o2_ = fmaf(w_, lm_ * za, ub_ + vl_) * (el1);              \
    float x2_ = fmaf(v_, (el0), x1_) * (eb1);                       \
    const bool p1_ = ((tcur) < ilen), p2_ = ((tcur) + 1 < ilen);    \
    aE = p2_ ? e2_ : (p1_ ? ub_ : aE);                              \
    aO = p2_ ? o2_ : (p1_ ? vl_ : aO);                              \
    aX = p2_ ? x2_ : (p1_ ? x1_ : aX);                              \
} while (0)

// --- backward single step --------------------------------------------------
#define BSTEP(el, eb) do {                                          \
    float t1_ = (el) * bO;                                          \
    float t2_ = (eb) * bE;                                          \
    float d_  = fmaf(t1_, za, t2_);                                 \
    float pd_ = __shfl_down_sync(0xffffffffu, d_, 1);               \
    float xb_ = (eb) * bX;                                          \
    if (lane == 31) pd_ = xb_;                                      \
    bE = t2_ + t1_; bO = t1_ + pd_; bX = xb_;                       \
} while (0)

#define BSTEPP(el, eb, ecur) do {                                   \
    float t1_ = (el) * bO;                                          \
    float t2_ = (eb) * bE;                                          \
    float d_  = fmaf(t1_, za, t2_);                                 \
    float pd_ = __shfl_down_sync(0xffffffffu, d_, 1);               \
    float xb_ = (eb) * bX;                                          \
    if (lane == 31) pd_ = xb_;                                      \
    float nE_ = t2_ + t1_, nO_ = t1_ + pd_;                         \
    if ((ecur) < ilen) { bE = nE_; bO = nO_; bX = xb_; }            \
} while (0)

// Single-instruction warp max via REDUX (positive floats: bit order = value order)
#define RENORM(r0, r1, r2, SH) do {                                 \
    float ml_ = fmaxf(fmaxf(r0, r1), r2);                           \
    unsigned mu_ = __reduce_max_sync(0xffffffffu,                   \
                                     __float_as_uint(ml_));         \
    if (mu_) {                                                      \
        const int e_ = (int)((mu_ >> 23) & 255u) - 127;             \
        int sh_ = RN_TARGET - e_;                                   \
        if (sh_ > 127)  sh_ = 127;                                  \
        if (sh_ < -126) sh_ = -126;                                 \
        const float sc_ = __int_as_float((127 + sh_) << 23);        \
        r0 *= sc_; r1 *= sc_; r2 *= sc_;                            \
        SH += sh_;                                                  \
    }                                                               \
} while (0)

// ---------------------------------------------------------------------------
// Fused kernel. Grid (33, 32), 128 threads.
// Phase 1 (all blocks): gather one (batch, class) column via ld.global.cg,
//   time-axis logsumexp, write linear emissions to g_emit[b][s][:].
// Phase 2 (last block per batch): warp0 forward alpha t=0..TH-1 (double-step),
//   warp1 backward beta over emissions TT-1..TH (single-step); dot-combine.
// ---------------------------------------------------------------------------
__global__ void __launch_bounds__(128, 8)
ctc_fused_kernel(const float* __restrict__ lp,
                 const int* __restrict__ targets,
                 const int* __restrict__ ilens,
                 const int* __restrict__ tlens,
                 float* __restrict__ out) {
    const int s   = blockIdx.x;   // 0..32
    const int b   = blockIdx.y;
    const int tid = threadIdx.x;  // 0..127

    __shared__ float redm[4], reds[4];
    __shared__ float fA[SS], fB[SS];
    __shared__ int   sSH[2];
    __shared__ int   sOld;

    // ---------------- Phase 1: gather + lse + linearize --------------------
    {
        const int c = (s < 32) ? targets[b * LL + s] : BLANK_ID;
        const float* col = lp + (size_t)b * TT * CC + c;

        float v[4];
#pragma unroll
        for (int k = 0; k < 4; ++k)
            v[k] = ldcg_(col + (size_t)(tid + k * 128) * CC);

        float m = fmaxf(fmaxf(v[0], v[1]), fmaxf(v[2], v[3]));
#pragma unroll
        for (int o = 16; o; o >>= 1) m = fmaxf(m, __shfl_xor_sync(0xffffffffu, m, o));
        const int w = tid >> 5;
        if ((tid & 31) == 0) redm[w] = m;
        __syncthreads();
        m = fmaxf(fmaxf(redm[0], redm[1]), fmaxf(redm[2], redm[3]));

        float sum = 0.f;
#pragma unroll
        for (int k = 0; k < 4; ++k) sum += ex2f_((v[k] - m) * LOG2E);
#pragma unroll
        for (int o = 16; o; o >>= 1) sum += __shfl_xor_sync(0xffffffffu, sum, o);
        if ((tid & 31) == 0) reds[w] = sum;
        __syncthreads();
        sum = reds[0] + reds[1] + reds[2] + reds[3];

        const float lse2 = m * LOG2E + lg2f_(sum);

        float* dst = g_emit + ((size_t)b * NSC + s) * TT;
#pragma unroll
        for (int k = 0; k < 4; ++k)
            dst[tid + k * 128] = ex2f_(v[k] * LOG2E - lse2 + CSHIFT);
    }

    __threadfence();
    __syncthreads();
    if (tid == 0) sOld = atomicAdd(&g_cnt[b], 1);
    __syncthreads();
    if (sOld != NSC - 1) return;     // not the last gather block for batch b

    // ---------------- Phase 2: recursion (winner block only) ---------------
    const int wid  = tid >> 5;
    const int lane = tid & 31;
    const float* em = g_emit + (size_t)b * NSC * TT;

    const int tgt = targets[b * LL + lane];
    const int tm1 = (lane > 0) ? targets[b * LL + lane - 1] : BLANK_ID;
    const int tm2 = (lane > 1) ? targets[b * LL + lane - 2] : BLANK_ID;
    const float za  = (lane > 0 && tgt != BLANK_ID && tgt != tm1) ? 1.f : 0.f;
    const float pza = (lane > 1 && tm1 != BLANK_ID && tm1 != tm2) ? 1.f : 0.f;
    const float zb  = (lane > 0) ? 1.f : 0.f;
    int ilen = ilens[b];
    if (ilen > TT) ilen = TT;

    const float* pL = em + (size_t)lane * TT;   // lane's label emissions
    const float* pB = em + (size_t)32  * TT;    // blank emissions (broadcast)

    if (wid == 0) {
        // ----- forward: alpha, t = 0 .. TH-1, double-stepped -----
        float aE = (lane == 0) ? 1.f : 0.f;     // virtual alpha_{-1}
        float aO = 0.f, aX = 0.f;
        int SH = 0;

        float4 La = ldcg4_(pL + 0), Ba = ldcg4_(pB + 0);
        float4 Lb = ldcg4_(pL + 4), Bb = ldcg4_(pB + 4);

#pragma unroll 2
        for (int g = 0; g < TH / 8; ++g) {      // 38 groups of 8 t (4 double steps)
            const int t0 = 8 * g;
            const float4 nLa = ldcg4_(pL + t0 + 8);
            const float4 nBa = ldcg4_(pB + t0 + 8);
            const float4 nLb = ldcg4_(pL + t0 + 12);
            const float4 nBb = ldcg4_(pB + t0 + 12);

            if (t0 + 7 < ilen) {
                FDS(La.x, La.y, Ba.x, Ba.y);
                FDS(La.z, La.w, Ba.z, Ba.w);
                FDS(Lb.x, Lb.y, Bb.x, Bb.y);
                FDS(Lb.z, Lb.w, Bb.z, Bb.w);
            } else {
                FDSP(La.x, La.y, Ba.x, Ba.y, t0 + 0);
                FDSP(La.z, La.w, Ba.z, Ba.w, t0 + 2);
                FDSP(Lb.x, Lb.y, Bb.x, Bb.y, t0 + 4);
                FDSP(Lb.z, Lb.w, Bb.z, Bb.w, t0 + 6);
            }
            if (g & 1) RENORM(aE, aO, aX, SH);  // every 16 t
            La = nLa; Ba = nBa; Lb = nLb; Bb = nBb;
        }

        fA[2 * lane] = aE;
        fA[2 * lane + 1] = aO;
        if (lane == 31) fA[64] = aX;
        if (lane == 0)  sSH[0] = SH;
    } else if (wid == 1) {
        // ----- backward: beta, consuming emissions e = TT-1 down to TH -----
        const int tl = tlens[b];
        const int i1 = 2 * tl;
        const int i2 = (2 * tl - 1 > 0) ? (2 * tl - 1) : 0;
        float bE = ((2 * lane == i1) || (2 * lane == i2)) ? 1.f : 0.f;
        float bO = (2 * lane + 1 == i2) ? 1.f : 0.f;
        float bX = (i1 == 64) ? 1.f : 0.f;   // only lane 31's copy is used
        int SH = 0;

        float4 La = ldcg4_(pL + TT - 4), Ba = ldcg4_(pB + TT - 4);
        float4 Lb = ldcg4_(pL + TT - 8), Bb = ldcg4_(pB + TT - 8);

#pragma unroll 2
        for (int g = 0; g < (TT - TH) / 8; ++g) {   // 26 groups of 8 emissions
            const int ea = TT - 4 - 8 * g;          // group A covers e = ea+3..ea
            const float4 nLa = ldcg4_(pL + ea - 8);
            const float4 nBa = ldcg4_(pB + ea - 8);
            const float4 nLb = ldcg4_(pL + ea - 12);
            const float4 nBb = ldcg4_(pB + ea - 12);

            if (ea + 3 < ilen) {
                BSTEP(La.w, Ba.w); BSTEP(La.z, Ba.z);
                BSTEP(La.y, Ba.y); BSTEP(La.x, Ba.x);
                BSTEP(Lb.w, Bb.w); BSTEP(Lb.z, Bb.z);
                BSTEP(Lb.y, Bb.y); BSTEP(Lb.x, Bb.x);
            } else {
                BSTEPP(La.w, Ba.w, ea + 3); BSTEPP(La.z, Ba.z, ea + 2);
                BSTEPP(La.y, Ba.y, ea + 1); BSTEPP(La.x, Ba.x, ea + 0);
                BSTEPP(Lb.w, Bb.w, ea - 1); BSTEPP(Lb.z, Bb.z, ea - 2);
                BSTEPP(Lb.y, Bb.y, ea - 3); BSTEPP(Lb.x, Bb.x, ea - 4);
            }
            if (g & 1) RENORM(bE, bO, bX, SH);      // every 16 t
            La = nLa; Ba = nBa; Lb = nLb; Bb = nBb;
        }

        fB[2 * lane] = bE;
        fB[2 * lane + 1] = bO;
        if (lane == 31) fB[64] = bX;
        if (lane == 0)  sSH[1] = SH;
    }

    __syncthreads();

    if (wid == 0) {
        // dot(alpha_{TH-1}, beta_{TH-1})
        float prod = fA[2 * lane] * fB[2 * lane]
                   + fA[2 * lane + 1] * fB[2 * lane + 1];
        if (lane == 31) prod = fmaf(fA[64], fB[64], prod);
#pragma unroll
        for (int o = 16; o; o >>= 1) prod += __shfl_xor_sync(0xffffffffu, prod, o);

        if (lane == 0) {
            const float tot = prod;
            float loss;
            if (tot > 0.f) {
                // stored = true * 2^(CSHIFT*ilen + SHa + SHb)
                const double ll2 = (double)lg2f_(tot)
                                 - (double)(sSH[0] + sSH[1])
                                 - (double)CSHIFT * (double)ilen;
                loss = (float)(-LN2d * ll2);
                if (!(loss < 1e20f)) loss = 0.f;   // zero_infinity
            } else {
                loss = 0.f;
            }
            const int tl = tlens[b];
            const int dn = (tl > 1) ? tl : 1;
            g_partial[b] = loss / (float)dn;
            g_cnt[b] = 0;                          // reset for next replay
            __threadfence();
        }
        __syncwarp();

        // deterministic last-batch mean (fixed-tree, counter reset)
        int old = 0;
        if (lane == 0) old = atomicAdd(&g_done, 1);
        old = __shfl_sync(0xffffffffu, old, 0);
        if (old == BB - 1) {
            float v = *((volatile float*)&g_partial[lane]);
#pragma unroll
            for (int o = 16; o; o >>= 1) v += __shfl_xor_sync(0xffffffffu, v, o);
            if (lane == 0) {
                out[0] = v * (1.0f / (float)BB);
                g_done = 0;                        // reset for next replay
            }
        }
    }
}

extern "C" void kernel_launch(void* const* d_in, const int* in_sizes, int n_in,
                              void* d_out, int out_size) {
    const float* lp      = (const float*)d_in[0];
    const int*   targets = (const int*)d_in[1];
    const int*   ilens   = (const int*)d_in[2];
    const int*   tlens   = (const int*)d_in[3];
    (void)in_sizes; (void)n_in; (void)out_size;

    ctc_fused_kernel<<<dim3(NSC, BB), 128>>>(lp, targets, ilens, tlens,
                                             (float*)d_out);
}